// round 11
// baseline (speedup 1.0000x reference)
#include <cuda_runtime.h>
#include <math.h>

#define THREADS 512
#define NBLOCKS 128
#define T 128

typedef unsigned long long F2;

__device__ __forceinline__ F2 pk2(float lo, float hi) {
    F2 r; asm("mov.b64 %0,{%1,%2};" : "=l"(r) : "f"(lo), "f"(hi)); return r;
}
__device__ __forceinline__ void upk2(F2 v, float& lo, float& hi) {
    asm("mov.b64 {%0,%1},%2;" : "=f"(lo), "=f"(hi) : "l"(v));
}
__device__ __forceinline__ F2 fma2(F2 a, F2 b, F2 c) {
    F2 d; asm("fma.rn.f32x2 %0,%1,%2,%3;" : "=l"(d) : "l"(a), "l"(b), "l"(c)); return d;
}
__device__ __forceinline__ F2 add2(F2 a, F2 b) {
    F2 d; asm("add.rn.f32x2 %0,%1,%2;" : "=l"(d) : "l"(a), "l"(b)); return d;
}
__device__ __forceinline__ F2 dup2(float w) { return pk2(w, w); }

__device__ __forceinline__ float tanh_fast(float x) {
    float e = __expf(2.0f * x);
    return 1.0f - __fdividef(2.0f, e + 1.0f);
}

// ---- smem float offsets ----
#define OFF_W1   0        // 2048
#define OFF_W2   2048     // 4096
#define OFF_HW   6144     // 2048  HW[j][c] pad32
#define OFF_E1W  8192     // 64
#define OFF_E1B  8256     // 64
#define OFF_E2T  8320     // 544
#define OFF_E2B  8864     // 8
#define OFF_B1   8872     // 64
#define OFF_B2   8936     // 64
#define OFF_INIT 9000     // 32
#define OFF_HB   9032     // 32
#define OFF_RES  9064     // 128 [32 seq][4 step-slot]
#define W_TOT    9192

// per-octet shared (float offsets)
#define O_TMP   0         // F2 [sp8][32]         512 f
#define O_TH    512       // F2 [s4][sp8][32]     2048 f
#define O_PART  2560      // F2 [chunk8][sp8][32] 4096 f  (phi: overlaid by hdS)
#define O_E     6656      // float [s4][seq16][8] 512 f
#define O_X     7168      // float [5][16] pad    96 f
#define OCT_SZ  7264

#define P_H1SZ 512        // per-warp F2 [q4][64] (h1, then h2 overlay)

#define SMEM_FLOATS (W_TOT + 2*OCT_SZ + 16*P_H1SZ)   // 31912 f = 127.6 KB

__global__ void __launch_bounds__(THREADS, 1) wfa_kernel(
    const float* __restrict__ x,
    const float* __restrict__ enc1_w, const float* __restrict__ enc1_b,
    const float* __restrict__ enc2_w, const float* __restrict__ enc2_b,
    const float* __restrict__ A_g,
    const float* __restrict__ init_w,
    const float* __restrict__ n1w, const float* __restrict__ n1b,
    const float* __restrict__ n2w, const float* __restrict__ n2b,
    const float* __restrict__ mu_w, const float* __restrict__ mu_b,
    const float* __restrict__ sg_w, const float* __restrict__ sg_b,
    const float* __restrict__ al_w, const float* __restrict__ al_b,
    float* __restrict__ out)
{
    extern __shared__ float sm[];
    const int tid = threadIdx.x;

    // ---- stage weights ----
    for (int i = tid; i < 2048; i += THREADS) sm[OFF_W1 + i] = n1w[i];
    for (int i = tid; i < 4096; i += THREADS) sm[OFF_W2 + i] = n2w[i];
    for (int i = tid; i < 2048; i += THREADS) {
        int j = i >> 5, c = i & 31;
        float v = 0.0f;
        if (c < 10)      v = mu_w[j * 10 + c];
        else if (c < 20) v = sg_w[j * 10 + (c - 10)];
        else if (c < 30) v = al_w[j * 10 + (c - 20)];
        sm[OFF_HW + i] = v;
    }
    for (int i = tid; i < 544; i += THREADS) {
        int d = i / 68, ii = i % 68;
        sm[OFF_E2T + i] = (ii < 64) ? enc2_w[ii * 8 + d] : 0.0f;
    }
    if (tid < 64) {
        sm[OFF_E1W + tid] = enc1_w[tid];
        sm[OFF_E1B + tid] = enc1_b[tid];
        sm[OFF_B1 + tid]  = n1b[tid];
        sm[OFF_B2 + tid]  = n2b[tid];
    }
    if (tid < 8)  sm[OFF_E2B + tid]  = enc2_b[tid];
    if (tid < 32) sm[OFF_INIT + tid] = init_w[tid];
    if (tid < 32) {
        int c = tid; float v = 0.0f;
        if (c < 10)      v = mu_b[c];
        else if (c < 20) v = sg_b[c - 10];
        else if (c < 30) v = al_b[c - 20];
        sm[OFF_HB + c] = v;
    }
    __syncthreads();

    const unsigned FULL = 0xffffffffu;
    const int wid = tid >> 5;
    const int l   = tid & 31;
    const int oct = wid >> 3;          // 0..1
    const int w   = wid & 7;           // warp within octet
    const int barid = 1 + oct;

    float* qm = sm + W_TOT + oct * OCT_SZ;
    F2* tmpS  = (F2*)(qm + O_TMP);     // [sp*32 + j]
    F2* thS   = (F2*)(qm + O_TH);      // [(s*8+sp)*32 + j]
    F2* partS = (F2*)(qm + O_PART);    // [(chunk*8+sp)*32 + l]
    float* eSf = qm + O_E;             // [s*128 + seq*8 + d]
    float* xSf = qm + O_X;             // [slot*16 + seq]

    F2* h1S = (F2*)(sm + W_TOT + 2 * OCT_SZ + wid * P_H1SZ);  // [q*64 + o]
    F2* hdS = (F2*)(qm + O_PART) + w * 128;                   // overlay: [q*32 + c]
    float* hdf = (float*)hdS;

    // ---- register caches ----
    // A chunk: i = 4w..4w+3, d-packed
    F2 Areg2[4][4];
    #pragma unroll
    for (int k = 0; k < 4; k++) {
        const int i = w * 4 + k;
        #pragma unroll
        for (int dp = 0; dp < 4; dp++) {
            float a0 = __ldg(&A_g[i * 256 + (2 * dp) * 32 + l]);
            float a1 = __ldg(&A_g[i * 256 + (2 * dp + 1) * 32 + l]);
            Areg2[k][dp] = pk2(a0, a1);
        }
    }
    const F2 B1a = dup2(sm[OFF_B1 + 2 * l]);
    const F2 B1b = dup2(sm[OFF_B1 + 2 * l + 1]);
    const F2 B2a = dup2(sm[OFF_B2 + 2 * l]);
    const F2 B2b = dup2(sm[OFF_B2 + 2 * l + 1]);
    const F2 HBd = dup2(sm[OFF_HB + l]);

    // encoder role: g = w*32+l in 0..255 -> (seq,d) twice (steps g>>7 and +2)
    const int e_g   = w * 32 + l;
    const int e_seq = (e_g & 127) >> 3;
    const int e_d   = e_g & 7;
    const int e_s   = e_g >> 7;              // 0 or 1; also does e_s+2
    const float e2b = sm[OFF_E2B + e_d];

    // phi role: warp w handles rows (s=w>>1, sp=(w&1)*4 .. +4)
    const F2* thB = thS + ((w >> 1) * 8 + (w & 1) * 4) * 32;

    // mixture role: step s_m, 4 lanes per seq, k-split 3/3/2/2
    const int s_m   = w >> 1;
    const int seqm  = (w & 1) * 8 + (l >> 2);
    const int qloc  = l >> 3;                // 0..3
    const int pe_m  = (l >> 2) & 1;
    const int kpart = l & 3;
    const int kstart = (kpart < 2) ? kpart * 3 : 2 + kpart * 2;  // 0,3,6,8
    const int kcount = (kpart < 2) ? 3 : 2;
    const int hdbase = qloc * 64 + pe_m;

    const int n0 = blockIdx.x * 32 + oct * 16;
    const float HALF_LOG2PI = 0.9189385332046727f;

    // ---- init state: warp w owns sp = w ----
    F2 tmpP = dup2(sm[OFF_INIT + l]);
    tmpS[w * 32 + l] = tmpP;

    float res = 0.0f;
    float xlast = 0.0f;

    #pragma unroll 1
    for (int it = 0; it < 32; it++) {
        asm volatile("bar.sync %0, 256;" :: "r"(barid) : "memory");   // A

        // ---- stage x: warps 0,1 load 64 values; warp 0 lanes<16 write slot0 ----
        if (w < 2) {
            if (w == 0 && l < 16) xSf[l] = xlast;
            const int task = w * 32 + l;      // 0..63
            const int s = task >> 4, sq = task & 15;
            xSf[(s + 1) * 16 + sq] = __ldg(&x[(size_t)(n0 + sq) * T + it * 4 + s]);
        }
        asm volatile("bar.sync %0, 256;" :: "r"(barid) : "memory");   // B
        if (w == 0 && l < 16) xlast = xSf[64 + l];

        // ---- encoder: every lane does 2 (seq,d,step) dots of length 64 ----
        {
            const float xA = xSf[e_s * 16 + e_seq];
            const float xB = xSf[(e_s + 2) * 16 + e_seq];
            float accA = 0.f, accB = 0.f;
            const float* Et = sm + OFF_E2T + e_d * 68;
            #pragma unroll 4
            for (int i = 0; i < 64; i += 4) {
                float4 wv = *(const float4*)&sm[OFF_E1W + i];
                float4 bv = *(const float4*)&sm[OFF_E1B + i];
                float4 tv = *(const float4*)&Et[i];
                float h;
                h = fmaxf(fmaf(xA, wv.x, bv.x), 0.f); accA = fmaf(h, tv.x, accA);
                h = fmaxf(fmaf(xB, wv.x, bv.x), 0.f); accB = fmaf(h, tv.x, accB);
                h = fmaxf(fmaf(xA, wv.y, bv.y), 0.f); accA = fmaf(h, tv.y, accA);
                h = fmaxf(fmaf(xB, wv.y, bv.y), 0.f); accB = fmaf(h, tv.y, accB);
                h = fmaxf(fmaf(xA, wv.z, bv.z), 0.f); accA = fmaf(h, tv.z, accA);
                h = fmaxf(fmaf(xB, wv.z, bv.z), 0.f); accB = fmaf(h, tv.z, accB);
                h = fmaxf(fmaf(xA, wv.w, bv.w), 0.f); accA = fmaf(h, tv.w, accA);
                h = fmaxf(fmaf(xB, wv.w, bv.w), 0.f); accB = fmaf(h, tv.w, accB);
            }
            eSf[e_s * 128 + e_seq * 8 + e_d]       = tanh_fast(accA + e2b);
            eSf[(e_s + 2) * 128 + e_seq * 8 + e_d] = tanh_fast(accB + e2b);
        }
        asm volatile("bar.sync %0, 256;" :: "r"(barid) : "memory");   // C

        // ---- 4 sequential micro-steps ----
        #pragma unroll 1
        for (int s = 0; s < 4; s++) {
            if (it * 4 + s > 0) {
                // partials: warp's 4-i chunk x all 8 sp, e-combined
                #pragma unroll 1
                for (int sp = 0; sp < 8; sp++) {
                    const F2* tr = &tmpS[sp * 32 + 4 * w];
                    ulonglong2 t01 = *(const ulonglong2*)&tr[0];
                    ulonglong2 t23 = *(const ulonglong2*)&tr[2];
                    F2 tF[4] = {t01.x, t01.y, t23.x, t23.y};
                    F2 ua0 = 0, ua1 = 0, ua2 = 0, ua3 = 0;
                    F2 ub0 = 0, ub1 = 0, ub2 = 0, ub3 = 0;
                    #pragma unroll
                    for (int k = 0; k < 4; k++) {
                        float ta, tb; upk2(tF[k], ta, tb);
                        F2 da = dup2(ta), db = dup2(tb);
                        ua0 = fma2(da, Areg2[k][0], ua0);
                        ua1 = fma2(da, Areg2[k][1], ua1);
                        ua2 = fma2(da, Areg2[k][2], ua2);
                        ua3 = fma2(da, Areg2[k][3], ua3);
                        ub0 = fma2(db, Areg2[k][0], ub0);
                        ub1 = fma2(db, Areg2[k][1], ub1);
                        ub2 = fma2(db, Areg2[k][2], ub2);
                        ub3 = fma2(db, Areg2[k][3], ub3);
                    }
                    const float* ea = &eSf[(s * 16 + 2 * sp) * 8];
                    ulonglong2 ev = *(const ulonglong2*)&ea[0];
                    ulonglong2 ew = *(const ulonglong2*)&ea[4];
                    ulonglong2 fv = *(const ulonglong2*)&ea[8];
                    ulonglong2 fw = *(const ulonglong2*)&ea[12];
                    F2 wa = 0, wb = 0;
                    wa = fma2(ev.x, ua0, wa); wa = fma2(ev.y, ua1, wa);
                    wa = fma2(ew.x, ua2, wa); wa = fma2(ew.y, ua3, wa);
                    wb = fma2(fv.x, ub0, wb); wb = fma2(fv.y, ub1, wb);
                    wb = fma2(fw.x, ub2, wb); wb = fma2(fw.y, ub3, wb);
                    float wa0, wa1, wb0, wb1;
                    upk2(wa, wa0, wa1); upk2(wb, wb0, wb1);
                    partS[(w * 8 + sp) * 32 + l] = pk2(wa0 + wa1, wb0 + wb1);
                }
                asm volatile("bar.sync %0, 256;" :: "r"(barid) : "memory");  // D
                // combine sp = w: sum over 8 chunks
                {
                    F2 v0 = add2(partS[(0 * 8 + w) * 32 + l], partS[(1 * 8 + w) * 32 + l]);
                    F2 v1 = add2(partS[(2 * 8 + w) * 32 + l], partS[(3 * 8 + w) * 32 + l]);
                    F2 v2 = add2(partS[(4 * 8 + w) * 32 + l], partS[(5 * 8 + w) * 32 + l]);
                    F2 v3 = add2(partS[(6 * 8 + w) * 32 + l], partS[(7 * 8 + w) * 32 + l]);
                    tmpP = add2(add2(v0, v1), add2(v2, v3));
                }
            }
            // publish tmp + tanh(tmp) for sp = w
            tmpS[w * 32 + l] = tmpP;
            {
                float ta, tb; upk2(tmpP, ta, tb);
                thS[(s * 8 + w) * 32 + l] = pk2(tanh_fast(ta), tanh_fast(tb));
            }
            asm volatile("bar.sync %0, 256;" :: "r"(barid) : "memory");      // E
        }

        // ===== phi: warp w processes its 4 rows (q-pairs) =====
        // --- W1: 32 -> 64, lane owns o = 2l, 2l+1 ---
        {
            F2 hA[4], hB[4];
            #pragma unroll
            for (int q = 0; q < 4; q++) { hA[q] = B1a; hB[q] = B1b; }
            #pragma unroll 2
            for (int ii = 0; ii < 16; ii++) {
                const int i = ii * 2;
                float2 w0 = *(const float2*)&sm[OFF_W1 + i * 64 + 2 * l];
                float2 w1 = *(const float2*)&sm[OFF_W1 + (i + 1) * 64 + 2 * l];
                F2 w00 = dup2(w0.x), w01 = dup2(w0.y), w10 = dup2(w1.x), w11 = dup2(w1.y);
                #pragma unroll
                for (int q = 0; q < 4; q++) {
                    ulonglong2 v = *(const ulonglong2*)&thB[q * 32 + i];
                    hA[q] = fma2(v.x, w00, hA[q]);
                    hB[q] = fma2(v.x, w01, hB[q]);
                    hA[q] = fma2(v.y, w10, hA[q]);
                    hB[q] = fma2(v.y, w11, hB[q]);
                }
            }
            #pragma unroll
            for (int q = 0; q < 4; q++) {
                float a, b;
                upk2(hA[q], a, b); F2 p0 = pk2(fmaxf(a, 0.f), fmaxf(b, 0.f));
                upk2(hB[q], a, b); F2 p1 = pk2(fmaxf(a, 0.f), fmaxf(b, 0.f));
                ulonglong2 st; st.x = p0; st.y = p1;
                *(ulonglong2*)&h1S[q * 64 + 2 * l] = st;
            }
        }
        __syncwarp();

        // --- W2: 64 -> 64 (reads h1S, overlays h2 back into h1S) ---
        {
            F2 hA[4], hB[4];
            #pragma unroll
            for (int q = 0; q < 4; q++) { hA[q] = B2a; hB[q] = B2b; }
            #pragma unroll 2
            for (int kk = 0; kk < 32; kk++) {
                const int k = kk * 2;
                float2 w0 = *(const float2*)&sm[OFF_W2 + k * 64 + 2 * l];
                float2 w1 = *(const float2*)&sm[OFF_W2 + (k + 1) * 64 + 2 * l];
                F2 w00 = dup2(w0.x), w01 = dup2(w0.y), w10 = dup2(w1.x), w11 = dup2(w1.y);
                #pragma unroll
                for (int q = 0; q < 4; q++) {
                    ulonglong2 v = *(const ulonglong2*)&h1S[q * 64 + k];
                    hA[q] = fma2(v.x, w00, hA[q]);
                    hB[q] = fma2(v.x, w01, hB[q]);
                    hA[q] = fma2(v.y, w10, hA[q]);
                    hB[q] = fma2(v.y, w11, hB[q]);
                }
            }
            __syncwarp();
            #pragma unroll
            for (int q = 0; q < 4; q++) {
                float a, b;
                upk2(hA[q], a, b); F2 p0 = pk2(fmaxf(a, 0.f), fmaxf(b, 0.f));
                upk2(hB[q], a, b); F2 p1 = pk2(fmaxf(a, 0.f), fmaxf(b, 0.f));
                ulonglong2 st; st.x = p0; st.y = p1;
                *(ulonglong2*)&h1S[q * 64 + 2 * l] = st;
            }
        }
        __syncwarp();

        // --- heads: 64 -> 30, lane owns c = l, weights from smem (LDS.32) ---
        {
            F2 hd[4];
            #pragma unroll
            for (int q = 0; q < 4; q++) hd[q] = HBd;
            #pragma unroll 2
            for (int jj = 0; jj < 32; jj++) {
                const int j = jj * 2;
                F2 w0 = dup2(sm[OFF_HW + j * 32 + l]);
                F2 w1 = dup2(sm[OFF_HW + (j + 1) * 32 + l]);
                #pragma unroll
                for (int q = 0; q < 4; q++) {
                    ulonglong2 v = *(const ulonglong2*)&h1S[q * 64 + j];
                    hd[q] = fma2(v.x, w0, hd[q]);
                    hd[q] = fma2(v.y, w1, hd[q]);
                }
            }
            #pragma unroll
            for (int q = 0; q < 4; q++) hdS[q * 32 + l] = hd[q];
        }
        __syncwarp();

        // ===== mixture: 4 lanes per seq, comps k-split 3/3/2/2 =====
        {
            const float xt_m = xSf[(s_m + 1) * 16 + seqm];
            float ck[3], ak[3];
            float cmax = -1e30f, amax = -1e30f;
            #pragma unroll
            for (int kk = 0; kk < 3; kk++) {
                float cc = -1e30f, al = -1e30f;
                if (kk < kcount) {
                    const int k = kstart + kk;
                    float mu = hdf[hdbase + k * 2];
                    float sg = hdf[hdbase + (10 + k) * 2];
                    al       = hdf[hdbase + (20 + k) * 2];
                    float z = (xt_m - mu) * __expf(-sg);
                    cc = fmaf(z, -0.5f * z, al - sg) - HALF_LOG2PI;
                }
                ck[kk] = cc; ak[kk] = al;
                cmax = fmaxf(cmax, cc); amax = fmaxf(amax, al);
            }
            cmax = fmaxf(cmax, __shfl_xor_sync(FULL, cmax, 1));
            cmax = fmaxf(cmax, __shfl_xor_sync(FULL, cmax, 2));
            amax = fmaxf(amax, __shfl_xor_sync(FULL, amax, 1));
            amax = fmaxf(amax, __shfl_xor_sync(FULL, amax, 2));
            float sc = 0.0f, sa = 0.0f;
            #pragma unroll
            for (int kk = 0; kk < 3; kk++) {
                if (kk < kcount) {
                    sc += __expf(ck[kk] - cmax);
                    sa += __expf(ak[kk] - amax);
                }
            }
            sc += __shfl_xor_sync(FULL, sc, 1);
            sc += __shfl_xor_sync(FULL, sc, 2);
            sa += __shfl_xor_sync(FULL, sa, 1);
            sa += __shfl_xor_sync(FULL, sa, 2);
            res += (cmax + __logf(sc)) - (amax + __logf(sa));
        }
    }

    // ---- final: write per-(seq, step-slot) partials, reduce ----
    if (kpart == 0) sm[OFF_RES + (oct * 16 + seqm) * 4 + s_m] = res;
    __syncthreads();
    if (tid < 32) {
        const float* rb = sm + OFF_RES + tid * 4;
        out[blockIdx.x * 32 + tid] = expf(rb[0] + rb[1] + rb[2] + rb[3]);
    }
}

extern "C" void kernel_launch(void* const* d_in, const int* in_sizes, int n_in,
                              void* d_out, int out_size) {
    const float* x      = (const float*)d_in[0];
    const float* enc1_w = (const float*)d_in[1];
    const float* enc1_b = (const float*)d_in[2];
    const float* enc2_w = (const float*)d_in[3];
    const float* enc2_b = (const float*)d_in[4];
    const float* A      = (const float*)d_in[5];
    const float* init_w = (const float*)d_in[6];
    const float* n1w    = (const float*)d_in[7];
    const float* n1b    = (const float*)d_in[8];
    const float* n2w    = (const float*)d_in[9];
    const float* n2b    = (const float*)d_in[10];
    const float* mu_w   = (const float*)d_in[11];
    const float* mu_b   = (const float*)d_in[12];
    const float* sg_w   = (const float*)d_in[13];
    const float* sg_b   = (const float*)d_in[14];
    const float* al_w   = (const float*)d_in[15];
    const float* al_b   = (const float*)d_in[16];
    float* out = (float*)d_out;

    const int smem_bytes = SMEM_FLOATS * (int)sizeof(float);
    cudaFuncSetAttribute(wfa_kernel, cudaFuncAttributeMaxDynamicSharedMemorySize, smem_bytes);
    wfa_kernel<<<NBLOCKS, THREADS, smem_bytes>>>(
        x, enc1_w, enc1_b, enc2_w, enc2_b, A, init_w,
        n1w, n1b, n2w, n2b, mu_w, mu_b, sg_w, sg_b, al_w, al_b, out);
}